// round 11
// baseline (speedup 1.0000x reference)
#include <cuda_runtime.h>
#include <cuda_bf16.h>
#include <stdint.h>

// out[B=1024, W=201000] f32 one-hot triple scatter over zeros.
// Inputs: z f32 (unused), hID i32[1024], rID i32[1024], tID i32[1024].
//
// Persistent fused fill+scatter: 148 CTAs (1 per SM), each streams a
// contiguous ~5.6MB slice sequentially (DRAM row-friendly: 148 long write
// streams instead of ~1200 interleaved 32KB bursts), then overwrites the
// hot elements inside its slice.

#define ENTITIES_N  100000
#define RELATIONS_N 1000
#define WIDTH       201000                   // floats per row
#define BATCH       1024
#define TOTAL_F4    51456000u                // 1024*201000/4
#define GRID        148
#define THREADS     256
#define Q_F4        347676u                  // ceil(TOTAL_F4/148)

__global__ void __launch_bounds__(THREADS) persist_onehot_fill(
    const int* __restrict__ hID,
    const int* __restrict__ rID,
    const int* __restrict__ tID,
    float4* __restrict__ out4)
{
    const unsigned start = blockIdx.x * Q_F4;
    const unsigned end   = min(start + Q_F4, TOTAL_F4);

    // ---- Sequential streaming fill of this CTA's slice ----
    const float4 z = make_float4(0.f, 0.f, 0.f, 0.f);
    unsigned i = start + threadIdx.x;
    // Unrolled by 4 (stores are fire-and-forget; LSU paces).
    for (; i + 3u * THREADS < end; i += 4u * THREADS) {
        out4[i]               = z;
        out4[i +     THREADS] = z;
        out4[i + 2u * THREADS] = z;
        out4[i + 3u * THREADS] = z;
    }
    for (; i < end; i += THREADS)
        out4[i] = z;

    __syncthreads();   // all zeros in this slice issued before any 1.0

    // ---- Fused scatter: hot elements inside [start*4, end*4) ----
    const unsigned lo = start * 4u;
    const unsigned hi = end * 4u;
    const unsigned row0 = lo / (unsigned)WIDTH;
    const unsigned row1 = (hi - 1u) / (unsigned)WIDTH;
    const unsigned nrows = row1 - row0 + 1u;          // <= 8

    const unsigned t = threadIdx.x;
    if (t < nrows * 3u) {
        const unsigned row = row0 + t / 3u;
        const unsigned j   = t % 3u;
        const int* src = (j == 0) ? hID : (j == 1) ? rID : tID;
        const unsigned off = (j == 0) ? 0u
                           : (j == 1) ? (unsigned)ENTITIES_N
                                      : (unsigned)(ENTITIES_N + RELATIONS_N);
        const unsigned q = row * (unsigned)WIDTH + off + (unsigned)__ldg(&src[row]);
        if (q >= lo && q < hi)
            ((float*)out4)[q] = 1.0f;
    }
}

extern "C" void kernel_launch(void* const* d_in, const int* in_sizes, int n_in,
                              void* d_out, int out_size) {
    const int* hID = (const int*)d_in[1];
    const int* rID = (const int*)d_in[2];
    const int* tID = (const int*)d_in[3];
    persist_onehot_fill<<<GRID, THREADS>>>(hID, rID, tID, (float4*)d_out);
}

// round 12
// speedup vs baseline: 1.1403x; 1.1403x over previous
#include <cuda_runtime.h>
#include <cuda_bf16.h>
#include <stdint.h>

// out[B=1024, W=201000] f32 one-hot triple scatter over zeros.
// Inputs: z f32 (unused), hID i32[1024], rID i32[1024], tID i32[1024].
//
// Structure:
//   node A: cudaMemsetAsync — CE fill path (~7.9 TB/s; SM store kernels cap ~7.0).
//   node B: scatter writing FULL 32B sectors (st.global.v8.f32), avoiding the
//           partial-write sector fetch / ECC RMW that made 4B scattered stores
//           cost ~7.5us. Geometry guarantees each hot element's 32B sector is
//           exclusively owned: row stride 804000B, h/r boundary 400000B, and
//           r/t boundary 404000B are all 32B-aligned.

#define ENTITIES_N  100000
#define RELATIONS_N 1000
#define WIDTH       201000
#define BATCH       1024

__global__ void __launch_bounds__(256) scatter_ones_v8(
    const int* __restrict__ hID,
    const int* __restrict__ rID,
    const int* __restrict__ tID,
    float* __restrict__ out)
{
    const unsigned tid = blockIdx.x * 256u + threadIdx.x;   // [0, 4096)
    const unsigned row = tid >> 2;
    const unsigned j   = tid & 3u;
    if (j == 3u) return;   // 3 sectors per row

    const int* src = (j == 0) ? hID : (j == 1) ? rID : tID;
    const unsigned off = (j == 0) ? 0u
                       : (j == 1) ? (unsigned)ENTITIES_N
                                  : (unsigned)(ENTITIES_N + RELATIONS_N);

    const unsigned q   = row * (unsigned)WIDTH + off + (unsigned)__ldg(&src[row]);
    const unsigned sec = q & ~7u;        // 32B-aligned sector base (floats)
    const unsigned k   = q & 7u;

    // Full-sector value: 1.0 at position k, zeros elsewhere (sector is
    // exclusively ours, rest of it must be zero anyway).
    float f0 = (k == 0u) ? 1.0f : 0.0f;
    float f1 = (k == 1u) ? 1.0f : 0.0f;
    float f2 = (k == 2u) ? 1.0f : 0.0f;
    float f3 = (k == 3u) ? 1.0f : 0.0f;
    float f4 = (k == 4u) ? 1.0f : 0.0f;
    float f5 = (k == 5u) ? 1.0f : 0.0f;
    float f6 = (k == 6u) ? 1.0f : 0.0f;
    float f7 = (k == 7u) ? 1.0f : 0.0f;

    asm volatile(
        "st.global.v8.f32 [%0], {%1,%2,%3,%4,%5,%6,%7,%8};"
        :: "l"(out + sec),
           "f"(f0), "f"(f1), "f"(f2), "f"(f3),
           "f"(f4), "f"(f5), "f"(f6), "f"(f7)
        : "memory");
}

extern "C" void kernel_launch(void* const* d_in, const int* in_sizes, int n_in,
                              void* d_out, int out_size) {
    const int* hID = (const int*)d_in[1];
    const int* rID = (const int*)d_in[2];
    const int* tID = (const int*)d_in[3];
    float* out = (float*)d_out;

    // Bulk zero on the CE fill path.
    cudaMemsetAsync(d_out, 0, (size_t)out_size * sizeof(float), 0);

    // Full-sector one-hot scatter.
    scatter_ones_v8<<<16, 256>>>(hID, rID, tID, out);
}